// round 1
// baseline (speedup 1.0000x reference)
#include <cuda_runtime.h>
#include <math.h>

#define BATCH 8
#define CCH 192
#define HEADS 16
#define HD 12
#define HW 16384
#define NSPLIT 32
#define KCHUNK 512   // HW / NSPLIT

// ---------------- scratch (device globals; no allocation) ----------------
__device__ float g_Spart[BATCH * NSPLIT * CCH * CCH];   // 37.7 MB split-K partials
__device__ float g_S[BATCH * CCH * CCH];                // X X^T per batch
__device__ float g_Meff[BATCH * CCH * CCH];             // folded attn*Wv per batch
__device__ float g_Y[(size_t)BATCH * CCH * HW];         // attention output (pre-dwconv)
__device__ float g_Z[(size_t)BATCH * CCH * HW];         // dwconv output

// ---------------- kernel 1: S partials = X X^T over a K-chunk ----------------
// grid: (9 = 3x3 m/n tiles, NSPLIT, BATCH), block 256. 64x64 tile, 4x4 per thread.
__global__ void s_partial_kernel(const float* __restrict__ x) {
    const int tm = blockIdx.x / 3, tn = blockIdx.x % 3;
    const int ks = blockIdx.y, b = blockIdx.z;
    const float* Xb = x + (size_t)b * CCH * HW;
    const int p0 = ks * KCHUNK;

    __shared__ float As[16][68];
    __shared__ float Bs[16][68];

    const int t  = threadIdx.x;
    const int tx = t & 15, ty = t >> 4;
    const int lr = t >> 2, lc = (t & 3) * 4;  // 64 rows x 16 k per stage

    float acc[4][4] = {};

    for (int kk0 = 0; kk0 < KCHUNK; kk0 += 16) {
        float4 av = *(const float4*)(Xb + (size_t)(tm * 64 + lr) * HW + p0 + kk0 + lc);
        float4 bv = *(const float4*)(Xb + (size_t)(tn * 64 + lr) * HW + p0 + kk0 + lc);
        As[lc + 0][lr] = av.x; As[lc + 1][lr] = av.y; As[lc + 2][lr] = av.z; As[lc + 3][lr] = av.w;
        Bs[lc + 0][lr] = bv.x; Bs[lc + 1][lr] = bv.y; Bs[lc + 2][lr] = bv.z; Bs[lc + 3][lr] = bv.w;
        __syncthreads();
#pragma unroll
        for (int kk = 0; kk < 16; kk++) {
            float a[4], bb[4];
#pragma unroll
            for (int i = 0; i < 4; i++) a[i] = As[kk][ty * 4 + i];
#pragma unroll
            for (int j = 0; j < 4; j++) bb[j] = Bs[kk][tx * 4 + j];
#pragma unroll
            for (int i = 0; i < 4; i++)
#pragma unroll
                for (int j = 0; j < 4; j++) acc[i][j] += a[i] * bb[j];
        }
        __syncthreads();
    }

    float* sp = g_Spart + (size_t)(b * NSPLIT + ks) * CCH * CCH;
#pragma unroll
    for (int i = 0; i < 4; i++) {
        float4 v = make_float4(acc[i][0], acc[i][1], acc[i][2], acc[i][3]);
        *(float4*)(sp + (size_t)(tm * 64 + ty * 4 + i) * CCH + tn * 64 + tx * 4) = v;
    }
}

// ---------------- kernel 2: reduce split-K partials ----------------
__global__ void s_reduce_kernel() {
    int gid = blockIdx.x * blockDim.x + threadIdx.x;
    if (gid >= BATCH * CCH * CCH) return;
    int b = gid / (CCH * CCH), mn = gid % (CCH * CCH);
    float s = 0.f;
#pragma unroll 8
    for (int ks = 0; ks < NSPLIT; ks++)
        s += g_Spart[(size_t)(b * NSPLIT + ks) * CCH * CCH + mn];
    g_S[gid] = s;
}

// ---------------- kernel 3: per-(b,h) attention -> Meff ----------------
// G = Wq S Wk^T, qnorm^2 = diag(Wq S Wq^T), knorm^2 = diag(Wk S Wk^T),
// attn = softmax(G * temp / (qn kn)), Meff rows = attn @ Wv.
// grid (HEADS, BATCH), 192 threads. Smem strides padded to 196 to kill 32-way conflicts.
__global__ void attn_build_kernel(const float* __restrict__ w_qkv,
                                  const float* __restrict__ temperature) {
    const int h = blockIdx.x, b = blockIdx.y, t = threadIdx.x;

    __shared__ float sWq[HD][196];
    __shared__ float sWk[HD][196];
    __shared__ float sT[2 * HD][196];   // reused for Wv later
    __shared__ float sG[HD][HD];
    __shared__ float sAttn[HD][HD];
    __shared__ float sQn[HD], sKn[HD];

    for (int i = t; i < HD * CCH; i += 192) {
        int c = i / CCH, j = i % CCH;
        sWq[c][j] = w_qkv[(h * HD + c) * CCH + j];
        sWk[c][j] = w_qkv[(CCH + h * HD + c) * CCH + j];
    }
    __syncthreads();

    // T = [Wq;Wk] * S   (thread t owns column t)
    {
        float tq[HD] = {}, tk[HD] = {};
        const float* Sb = g_S + b * CCH * CCH;
        for (int m = 0; m < CCH; m++) {
            float s = Sb[m * CCH + t];
#pragma unroll
            for (int c = 0; c < HD; c++) { tq[c] += sWq[c][m] * s; tk[c] += sWk[c][m] * s; }
        }
#pragma unroll
        for (int c = 0; c < HD; c++) { sT[c][t] = tq[c]; sT[HD + c][t] = tk[c]; }
    }
    __syncthreads();

    // G and diagonal norms (168 tasks over 192 threads)
    if (t < 144) {
        int c = t / HD, d = t % HD;
        float s = 0.f;
        for (int j = 0; j < CCH; j++) s += sT[c][j] * sWk[d][j];
        sG[c][d] = s;
    } else if (t < 156) {
        int c = t - 144; float s = 0.f;
        for (int j = 0; j < CCH; j++) s += sT[c][j] * sWq[c][j];
        sQn[c] = s;
    } else if (t < 168) {
        int c = t - 156; float s = 0.f;
        for (int j = 0; j < CCH; j++) s += sT[HD + c][j] * sWk[c][j];
        sKn[c] = s;
    }
    __syncthreads();

    // softmax rows (threads 0..11) -- sT no longer needed, so all threads also load Wv
    if (t < HD) {
        float temp = temperature[h];
        float qn = fmaxf(sqrtf(fmaxf(sQn[t], 0.f)), 1e-12f);
        float lg[HD];
        float mx = -1e30f;
#pragma unroll
        for (int d = 0; d < HD; d++) {
            float kn = fmaxf(sqrtf(fmaxf(sKn[d], 0.f)), 1e-12f);
            lg[d] = sG[t][d] * temp / (qn * kn);
            mx = fmaxf(mx, lg[d]);
        }
        float sum = 0.f;
#pragma unroll
        for (int d = 0; d < HD; d++) { lg[d] = expf(lg[d] - mx); sum += lg[d]; }
        float inv = 1.f / sum;
#pragma unroll
        for (int d = 0; d < HD; d++) sAttn[t][d] = lg[d] * inv;
    }
    float (*sWv)[196] = sT;  // reuse
    for (int i = t; i < HD * CCH; i += 192) {
        int c = i / CCH, j = i % CCH;
        sWv[c][j] = w_qkv[(2 * CCH + h * HD + c) * CCH + j];
    }
    __syncthreads();

    // Meff rows for this head: Meff[h*12+c][j] = sum_d attn[c][d] * Wv[d][j]
#pragma unroll
    for (int c = 0; c < HD; c++) {
        float s = 0.f;
#pragma unroll
        for (int d = 0; d < HD; d++) s += sAttn[c][d] * sWv[d][t];
        g_Meff[(size_t)(b * CCH + h * HD + c) * CCH + t] = s;
    }
}

// ---------------- kernel 4: C[b] = A_b[192,192] @ B[b][192,HW] ----------------
// Used for Y = Meff @ X and out = Wproj @ Z (aStride=0 shares A across batches).
// grid (HW/64, 3, BATCH), block 256, 64x64 tile, 4x4 per thread, BK=16.
__global__ void gemm192_kernel(const float* __restrict__ A, int aStride,
                               const float* __restrict__ B, float* __restrict__ Cout) {
    const float* Ab = A + (size_t)blockIdx.z * aStride;
    const float* Bb = B + (size_t)blockIdx.z * CCH * HW;
    float* Cb = Cout + (size_t)blockIdx.z * CCH * HW;
    const int m0 = blockIdx.y * 64, n0 = blockIdx.x * 64;

    __shared__ float As[16][68];
    __shared__ float Bs[16][68];

    const int t  = threadIdx.x;
    const int tx = t & 15, ty = t >> 4;
    const int lr = t >> 2, lc = (t & 3) * 4;    // A: 64 rows x 16 k
    const int br = t >> 4, bc = (t & 15) * 4;   // B: 16 rows x 64 p

    float acc[4][4] = {};

    for (int k0 = 0; k0 < CCH; k0 += 16) {
        float4 av = *(const float4*)(Ab + (m0 + lr) * CCH + k0 + lc);
        As[lc + 0][lr] = av.x; As[lc + 1][lr] = av.y; As[lc + 2][lr] = av.z; As[lc + 3][lr] = av.w;
        float4 bv = *(const float4*)(Bb + (size_t)(k0 + br) * HW + n0 + bc);
        *(float4*)&Bs[br][bc] = bv;
        __syncthreads();
#pragma unroll
        for (int kk = 0; kk < 16; kk++) {
            float a[4], bb[4];
#pragma unroll
            for (int i = 0; i < 4; i++) a[i] = As[kk][ty * 4 + i];
#pragma unroll
            for (int j = 0; j < 4; j++) bb[j] = Bs[kk][tx * 4 + j];
#pragma unroll
            for (int i = 0; i < 4; i++)
#pragma unroll
                for (int j = 0; j < 4; j++) acc[i][j] += a[i] * bb[j];
        }
        __syncthreads();
    }
#pragma unroll
    for (int i = 0; i < 4; i++) {
        float4 v = make_float4(acc[i][0], acc[i][1], acc[i][2], acc[i][3]);
        *(float4*)(Cb + (size_t)(m0 + ty * 4 + i) * HW + n0 + tx * 4) = v;
    }
}

// ---------------- kernel 5: depthwise 3x3, pad 1 ----------------
// grid (4, 16, BATCH*CCH), block 256 = 32x8 pixels.
__global__ void dwconv_kernel(const float* __restrict__ wdw) {
    const int bc = blockIdx.z;
    const int c = bc % CCH;
    const int xx = blockIdx.x * 32 + (threadIdx.x & 31);
    const int yy = blockIdx.y * 8 + (threadIdx.x >> 5);
    const float* Yc = g_Y + (size_t)bc * HW;

    float w[9];
#pragma unroll
    for (int i = 0; i < 9; i++) w[i] = wdw[c * 9 + i];

    float acc = 0.f;
#pragma unroll
    for (int ky = 0; ky < 3; ky++) {
        int sy = yy + ky - 1;
        if (sy < 0 || sy >= 128) continue;
#pragma unroll
        for (int kx = 0; kx < 3; kx++) {
            int sx = xx + kx - 1;
            if (sx < 0 || sx >= 128) continue;
            acc += w[ky * 3 + kx] * __ldg(Yc + sy * 128 + sx);
        }
    }
    g_Z[(size_t)bc * HW + yy * 128 + xx] = acc;
}

// ---------------- launch ----------------
extern "C" void kernel_launch(void* const* d_in, const int* in_sizes, int n_in,
                              void* d_out, int out_size) {
    const float* x           = (const float*)d_in[0];
    const float* w_qkv       = (const float*)d_in[1];
    const float* w_dw        = (const float*)d_in[2];
    const float* w_proj      = (const float*)d_in[3];
    const float* temperature = (const float*)d_in[4];
    float* out = (float*)d_out;

    float *pMeff, *pY, *pZ;
    cudaGetSymbolAddress((void**)&pMeff, g_Meff);
    cudaGetSymbolAddress((void**)&pY, g_Y);
    cudaGetSymbolAddress((void**)&pZ, g_Z);

    // 1) S = X X^T (split-K partials + deterministic reduce)
    s_partial_kernel<<<dim3(9, NSPLIT, BATCH), 256>>>(x);
    s_reduce_kernel<<<(BATCH * CCH * CCH + 255) / 256, 256>>>();

    // 2) tiny: G, norms, softmax, Meff
    attn_build_kernel<<<dim3(HEADS, BATCH), 192>>>(w_qkv, temperature);

    // 3) Y = Meff @ X   (attention output, [b,192,HW])
    gemm192_kernel<<<dim3(HW / 64, 3, BATCH), 256>>>(pMeff, CCH * CCH, x, pY);

    // 4) depthwise 3x3
    dwconv_kernel<<<dim3(4, 16, BATCH * CCH), 256>>>(w_dw);

    // 5) out = Wproj @ Z
    gemm192_kernel<<<dim3(HW / 64, 3, BATCH), 256>>>(w_proj, 0, pZ, out);
}